// round 11
// baseline (speedup 1.0000x reference)
#include <cuda_runtime.h>
#include <cuda_bf16.h>
#include <stdint.h>

// ---------------------------------------------------------------------------
// RGCN layer on mma.sync bf16 (plain sm_103 target; tcgen05 PTX rejected by
// the harness's compute_103 stage):
//   S   = segsum_dst( x[src] @ W_rel[etype] )          (REDs into zeroed S)
//   mid = tanh( x @ (W1x + loop_w@W1m) + S @ W1m + (b1 + rel_bias@W1m) )
//   out = [x, mid] @ W2 + b2
// (loop_w / rel_bias folded into W1 — algebraically identical to reference)
//
//   * operands pre-split to bf16 (hi, lo); A@B = AhBh + AhBl + AlBh
//   * weights pre-transposed to [OUT, K]  (mma .row.col B layout)
//   * edges counting-sorted by relation, segments padded to 128
//   * 3-stage single-sync cp.async pipeline (K=32 stages, SW64 swizzle)
//   * CTA tile 128x64, warp tile 32x32, 3 CTAs/SM (24 warps: latency hiding)
//   * edge scatter: shfl-packed red.global.add.v4.f32 (L2-resident S)
// ---------------------------------------------------------------------------

#define N_MAX   100000
#define E_MAX   640000
#define R_MAX   8
#define PERM_PAD (R_MAX * 128)

__device__ float          g_msg  [(size_t)N_MAX * 128];      // S (edge sums)
__device__ __nv_bfloat16  g_xhi  [(size_t)N_MAX * 128];
__device__ __nv_bfloat16  g_xlo  [(size_t)N_MAX * 128];
__device__ __nv_bfloat16  g_msghi[(size_t)N_MAX * 128];
__device__ __nv_bfloat16  g_msglo[(size_t)N_MAX * 128];
__device__ __nv_bfloat16  g_midhi[(size_t)N_MAX * 256];
__device__ __nv_bfloat16  g_midlo[(size_t)N_MAX * 256];
__device__ __nv_bfloat16  g_wrelThi[R_MAX * 128 * 128];
__device__ __nv_bfloat16  g_wrelTlo[R_MAX * 128 * 128];
__device__ __nv_bfloat16  g_w1Thi[256 * 256];
__device__ __nv_bfloat16  g_w1Tlo[256 * 256];
__device__ __nv_bfloat16  g_w2Thi[128 * 384];
__device__ __nv_bfloat16  g_w2Tlo[128 * 384];
__device__ float          g_b1eff[256];
__device__ int g_perm[E_MAX + PERM_PAD];
__device__ int g_cnt[R_MAX];
__device__ int g_cur[R_MAX];

// ---- helpers ---------------------------------------------------------------
__device__ __forceinline__ uint32_t smem_u32(const void* p) {
    uint32_t a;
    asm("{ .reg .u64 t; cvta.to.shared.u64 t, %1; cvt.u32.u64 %0, t; }"
        : "=r"(a) : "l"(p));
    return a;
}

#define CPA16(sm, gp) \
    asm volatile("cp.async.cg.shared.global [%0], [%1], 16;" \
                 :: "r"(sm), "l"(gp) : "memory")
#define CPA_COMMIT() \
    asm volatile("cp.async.commit_group;" ::: "memory")
#define CPA_WAIT1() \
    asm volatile("cp.async.wait_group 1;" ::: "memory")
#define CPA_WAIT0() \
    asm volatile("cp.async.wait_group 0;" ::: "memory")

__device__ __forceinline__ void ldsm4(uint32_t* r, uint32_t addr) {
    asm volatile("ldmatrix.sync.aligned.m8n8.x4.shared.b16 {%0,%1,%2,%3}, [%4];"
        : "=r"(r[0]), "=r"(r[1]), "=r"(r[2]), "=r"(r[3]) : "r"(addr));
}
__device__ __forceinline__ void mma16816(float* d, const uint32_t* a,
                                         const uint32_t* b) {
    asm volatile(
        "mma.sync.aligned.m16n8k16.row.col.f32.bf16.bf16.f32 "
        "{%0,%1,%2,%3}, {%4,%5,%6,%7}, {%8,%9}, {%0,%1,%2,%3};"
        : "+f"(d[0]), "+f"(d[1]), "+f"(d[2]), "+f"(d[3])
        : "r"(a[0]), "r"(a[1]), "r"(a[2]), "r"(a[3]), "r"(b[0]), "r"(b[1]));
}
__device__ __forceinline__ float tanh_fast(float x) {
    float e;
    asm("ex2.approx.f32 %0, %1;" : "=f"(e) : "f"(x * 2.8853900817779268f));
    return 1.0f - __fdividef(2.0f, e + 1.0f);
}

// ---- fp32 -> (hi, lo) split; also zeroes S, g_cnt, g_cur -------------------
__global__ void k_split4(const float* __restrict__ in,
                         __nv_bfloat16* __restrict__ hi,
                         __nv_bfloat16* __restrict__ lo, int n4) {
    int i = blockIdx.x * blockDim.x + threadIdx.x;
    if (blockIdx.x == 0 && threadIdx.x < R_MAX) {
        g_cnt[threadIdx.x] = 0;
        g_cur[threadIdx.x] = 0;
    }
    if (i >= n4) return;
    ((float4*)g_msg)[i] = make_float4(0.f, 0.f, 0.f, 0.f);   // zero S
    float4 v = ((const float4*)in)[i];
    unsigned short h[4], l[4];
    float vv[4] = {v.x, v.y, v.z, v.w};
#pragma unroll
    for (int j = 0; j < 4; j++) {
        __nv_bfloat16 hb = __float2bfloat16(vv[j]);
        h[j] = __bfloat16_as_ushort(hb);
        l[j] = __bfloat16_as_ushort(__float2bfloat16(vv[j] - __bfloat162float(hb)));
    }
    uint2 hp, lp;
    hp.x = (uint32_t)h[0] | ((uint32_t)h[1] << 16);
    hp.y = (uint32_t)h[2] | ((uint32_t)h[3] << 16);
    lp.x = (uint32_t)l[0] | ((uint32_t)l[1] << 16);
    lp.y = (uint32_t)l[2] | ((uint32_t)l[3] << 16);
    ((uint2*)hi)[i] = hp;
    ((uint2*)lo)[i] = lp;
}

// ---- plain split (no side effects) for S -----------------------------------
__global__ void k_split4m(const float* __restrict__ in,
                          __nv_bfloat16* __restrict__ hi,
                          __nv_bfloat16* __restrict__ lo, int n4) {
    int i = blockIdx.x * blockDim.x + threadIdx.x;
    if (i >= n4) return;
    float4 v = ((const float4*)in)[i];
    unsigned short h[4], l[4];
    float vv[4] = {v.x, v.y, v.z, v.w};
#pragma unroll
    for (int j = 0; j < 4; j++) {
        __nv_bfloat16 hb = __float2bfloat16(vv[j]);
        h[j] = __bfloat16_as_ushort(hb);
        l[j] = __bfloat16_as_ushort(__float2bfloat16(vv[j] - __bfloat162float(hb)));
    }
    uint2 hp, lp;
    hp.x = (uint32_t)h[0] | ((uint32_t)h[1] << 16);
    hp.y = (uint32_t)h[2] | ((uint32_t)h[3] << 16);
    lp.x = (uint32_t)l[0] | ((uint32_t)l[1] << 16);
    lp.y = (uint32_t)l[2] | ((uint32_t)l[3] << 16);
    ((uint2*)hi)[i] = hp;
    ((uint2*)lo)[i] = lp;
}

// ---- all-relation weight transpose + split: [R,128,128] -> [R][O,K] --------
__global__ void k_prepwrel(const float* __restrict__ in) {
    int i = blockIdx.x * blockDim.x + threadIdx.x;
    if (i >= R_MAX * 128 * 128) return;
    int r = i >> 14, rem = i & 16383;
    int k = rem >> 7, o = rem & 127;
    float v = in[i];
    __nv_bfloat16 hb = __float2bfloat16(v);
    size_t idx = (size_t)r * 16384 + (size_t)o * 128 + k;
    g_wrelThi[idx] = hb;
    g_wrelTlo[idx] = __float2bfloat16(v - __bfloat162float(hb));
}

// ---- W2 transpose + split: [384, 128] -> [128, 384] ------------------------
__global__ void k_prepw2(const float* __restrict__ in) {
    int i = blockIdx.x * blockDim.x + threadIdx.x;
    if (i >= 384 * 128) return;
    int k = i >> 7, o = i & 127;
    float v = in[i];
    __nv_bfloat16 hb = __float2bfloat16(v);
    size_t idx = (size_t)o * 384 + k;
    g_w2Thi[idx] = hb;
    g_w2Tlo[idx] = __float2bfloat16(v - __bfloat162float(hb));
}

// ---- fold loop_w / rel_bias into W1 (fp32 exact), then split ---------------
__global__ void k_foldw1(const float* __restrict__ W1,
                         const float* __restrict__ loop_w,
                         const float* __restrict__ rel_bias,
                         const float* __restrict__ b1) {
    int i = blockIdx.x * blockDim.x + threadIdx.x;
    if (i < 256 * 256) {
        int k = i >> 8, o = i & 255;
        float s = W1[(size_t)k * 256 + o];
        if (k < 128) {
            const float* lw = loop_w + (size_t)k * 128;
#pragma unroll 4
            for (int j = 0; j < 128; j++)
                s += lw[j] * W1[(size_t)(128 + j) * 256 + o];
        }
        __nv_bfloat16 hb = __float2bfloat16(s);
        size_t idx = (size_t)o * 256 + k;
        g_w1Thi[idx] = hb;
        g_w1Tlo[idx] = __float2bfloat16(s - __bfloat162float(hb));
    } else if (i < 256 * 256 + 256) {
        int o = i - 256 * 256;
        float s = b1[o];
        for (int j = 0; j < 128; j++)
            s += rel_bias[j] * W1[(size_t)(128 + j) * 256 + o];
        g_b1eff[o] = s;
    }
}

// ---- sort: init perm + histogram (g_cnt pre-zeroed by k_split4) -----------
__global__ void k_inithist(const int* __restrict__ etype, int E, int P) {
    __shared__ int h[R_MAX];
    int tid = threadIdx.x;
    if (tid < R_MAX) h[tid] = 0;
    __syncthreads();
    int i = blockIdx.x * blockDim.x + tid;
    if (i < P) g_perm[i] = -1;
    if (i < E) atomicAdd(&h[etype[i]], 1);
    __syncthreads();
    if (tid < R_MAX && h[tid]) atomicAdd(&g_cnt[tid], h[tid]);
}
// scatter with per-block redundant padded-prefix (no separate scan launch)
__global__ void k_scatter(const int* __restrict__ etype, int E) {
    __shared__ int h[R_MAX], base[R_MAX], off[R_MAX];
    int tid = threadIdx.x;
    if (tid < R_MAX) {
        h[tid] = 0;
        int o = 0;
        for (int r = 0; r < tid; r++) o += (g_cnt[r] + 127) & ~127;
        off[tid] = o;
    }
    __syncthreads();
    int e = blockIdx.x * blockDim.x + tid;
    int r = -1, rank = 0;
    if (e < E) { r = etype[e]; rank = atomicAdd(&h[r], 1); }
    __syncthreads();
    if (tid < R_MAX && h[tid]) base[tid] = atomicAdd(&g_cur[tid], h[tid]);
    __syncthreads();
    if (e < E) g_perm[off[r] + base[r] + rank] = e;
}

// ---------------------------------------------------------------------------
// Unified HMMA GEMM. MODE: 1=edge(scatter into S), 2=MLP1, 3=MLP2
// 256 threads = 8 warps (4 m x 2 n); CTA tile 128x64; warp tile 32x32.
// K in 32-wide stages; per stage: A hi/lo 128rx64B + B hi/lo 64rx64B = 24KB,
// SW64 swizzle; THREE stage buffers, single __syncthreads per stage.
// 3 CTAs/SM (85-reg cap) -> 24 warps for latency hiding.
// ---------------------------------------------------------------------------
static constexpr int ATILE_B = 8192;                 // 128 rows x 64 B
static constexpr int BTILE_B = 4096;                 //  64 rows x 64 B
static constexpr int STAGE_B = 2 * ATILE_B + 2 * BTILE_B;   // 24 KB
static constexpr int NSTAGE  = 3;
static constexpr int SMEM_DYN = 128 + 2048 + NSTAGE * STAGE_B;

template<int MODE>
__global__ void __launch_bounds__(256, 3)
gemm_rgcn(const int* __restrict__ src, const int* __restrict__ dst,
          const int* __restrict__ etype,
          const float* __restrict__ bias,
          float* __restrict__ outp, int N)
{
    constexpr int CH   = (MODE == 2) ? 8 : (MODE == 3) ? 12 : 4;   // 32-k stages
    constexpr int KTOT = (MODE == 2) ? 256 : (MODE == 3) ? 384 : 128;

    extern __shared__ char dynsmem[];
    uint32_t sb0 = smem_u32(dynsmem);
    uint32_t sb  = (sb0 + 127) & ~127u;
    char* smp = dynsmem + (sb - sb0);

    const int tid = threadIdx.x;
    const int coloff = blockIdx.y * 64;
    const int rowbase = blockIdx.x * 128;
    int* s_meta = (int*)smp;
    int* s_src  = (int*)(smp + 16);
    int* s_dst  = (int*)(smp + 528);
    const uint32_t STG0 = sb + 2048;

    int rel = 0;
    if constexpr (MODE == 1) {
        if (tid < 128) {
            int e = g_perm[rowbase + tid];
            s_src[tid] = (e >= 0) ? src[e] : 0;
            s_dst[tid] = (e >= 0) ? dst[e] : -1;
            if (tid == 0) s_meta[0] = (e >= 0) ? etype[e] : -1;
        }
        __syncthreads();
        rel = s_meta[0];
        if (rel < 0) return;                 // fully-padded tile
    }

    // ---- loader geometry
    const int r0 = tid >> 2, qid = tid & 3;           // A rows r0, r0+64
    int arow0, arow1;
    if constexpr (MODE == 1) { arow0 = s_src[r0]; arow1 = s_src[r0 + 64]; }
    else {
        arow0 = rowbase + r0;      if (arow0 > N - 1) arow0 = N - 1;
        arow1 = rowbase + r0 + 64; if (arow1 > N - 1) arow1 = N - 1;
    }
    // SW64 swizzled smem offsets (chunk ^ ((row&6)<<3)); row+64 keeps (row&6)
    const uint32_t sd0 = (uint32_t)r0 * 64 + (uint32_t)((qid * 16) ^ ((r0 & 6) << 3));
    const uint32_t sd1 = sd0 + 64 * 64;
    const uint32_t sdb = sd0;                          // B row = r0 (0..63)

    // ---- fragment geometry (warp tile 32x32, warp grid 4m x 2n)
    const int L  = tid & 31, wid = tid >> 5;
    const int wm = (wid & 3) * 32, wn = (wid >> 2) * 32;
    const int lr15 = L & 15;
    const uint32_t swz = (uint32_t)((lr15 & 6) << 3);
    const uint32_t rowA = (uint32_t)(wm + lr15) * 64;
    const uint32_t rowB = (uint32_t)(wn + lr15) * 64;
    uint32_t cbx[2];
#pragma unroll
    for (int ks = 0; ks < 2; ks++)
        cbx[ks] = (uint32_t)(((L >> 4) * 16 + ks * 32)) ^ swz;

    float acc[2][4][4];
#pragma unroll
    for (int mi = 0; mi < 2; mi++)
#pragma unroll
        for (int ni = 0; ni < 4; ni++)
#pragma unroll
            for (int q = 0; q < 4; q++) acc[mi][ni][q] = 0.0f;

    // ---- stage issue: 6 x 16B cp.async into buffer (c % 3)
    auto issue = [&](int c) {
        const __nv_bfloat16 *pah, *pal, *pbh, *pbl;
        size_t ka, abase;
        if (MODE == 2 && c >= 4)      { pah = g_msghi; pal = g_msglo; ka = 128; abase = (size_t)(c - 4) * 32; }
        else if (MODE == 3 && c >= 4) { pah = g_midhi; pal = g_midlo; ka = 256; abase = (size_t)(c - 4) * 32; }
        else                          { pah = g_xhi;   pal = g_xlo;   ka = 128; abase = (size_t)c * 32; }
        if (MODE == 1)      { pbh = g_wrelThi + (size_t)rel * 16384; pbl = g_wrelTlo + (size_t)rel * 16384; }
        else if (MODE == 2) { pbh = g_w1Thi;   pbl = g_w1Tlo; }
        else                { pbh = g_w2Thi;   pbl = g_w2Tlo; }
        const size_t a0 = (size_t)arow0 * ka + abase + (size_t)qid * 8;
        const size_t a1 = (size_t)arow1 * ka + abase + (size_t)qid * 8;
        const size_t b0 = (size_t)(coloff + r0) * KTOT + (size_t)c * 32 + (size_t)qid * 8;
        const uint32_t ST = STG0 + (uint32_t)(c % NSTAGE) * STAGE_B;
        const uint32_t AH = ST, AL = ST + ATILE_B,
                       BH = ST + 2 * ATILE_B, BL = BH + BTILE_B;
        CPA16(AH + sd0, (const char*)(pah + a0));
        CPA16(AH + sd1, (const char*)(pah + a1));
        CPA16(AL + sd0, (const char*)(pal + a0));
        CPA16(AL + sd1, (const char*)(pal + a1));
        CPA16(BH + sdb, (const char*)(pbh + b0));
        CPA16(BL + sdb, (const char*)(pbl + b0));
        CPA_COMMIT();
    };

    issue(0);
    issue(1);

#pragma unroll 1
    for (int c = 0; c < CH; ++c) {
        if (c + 1 < CH) CPA_WAIT1(); else CPA_WAIT0();
        __syncthreads();           // stage c ready; all warps done with c-1
        if (c + 2 < CH) issue(c + 2);   // writes (c+2)%3 == (c-1)%3: safe

        const uint32_t ST = STG0 + (uint32_t)(c % NSTAGE) * STAGE_B;
        const uint32_t AH = ST, AL = ST + ATILE_B,
                       BH = ST + 2 * ATILE_B, BL = BH + BTILE_B;

        // fragment-reuse 3-pass: load Ah,Bh,Bl -> AhBh + AhBl; load Al -> AlBh
#pragma unroll
        for (int ks = 0; ks < 2; ++ks) {
            const uint32_t ko = cbx[ks];
            uint32_t aF[2][4], bHf[4][2], bLf[4][2];
            {
                uint32_t bq[4], bq2[4];
                ldsm4(bq,  BH + rowB + ko);
                ldsm4(bq2, BH + rowB + 1024 + ko);
                bHf[0][0] = bq[0];  bHf[0][1] = bq[2];
                bHf[1][0] = bq[1];  bHf[1][1] = bq[3];
                bHf[2][0] = bq2[0]; bHf[2][1] = bq2[2];
                bHf[3][0] = bq2[1]; bHf[3][1] = bq2[3];
                ldsm4(bq,  BL + rowB + ko);
                ldsm4(bq2, BL + rowB + 1024 + ko);
                bLf[0][0] = bq[0];  bLf[0][1] = bq[2];
                bLf[1][0] = bq[1];  bLf[1][1] = bq[3];
                bLf[2][0] = bq2[0]; bLf[2][1] = bq2[2];
                bLf[3][0] = bq2[1]; bLf[3][1] = bq2[3];
            }
#pragma unroll
            for (int mi = 0; mi < 2; ++mi)
                ldsm4(aF[mi], AH + rowA + mi * 1024 + ko);
#pragma unroll
            for (int mi = 0; mi < 2; ++mi)
#pragma unroll
                for (int ni = 0; ni < 4; ++ni)
                    mma16816(acc[mi][ni], aF[mi], bHf[ni]);
#pragma unroll
            for (int mi = 0; mi < 2; ++mi)
#pragma unroll
                for (int ni = 0; ni < 4; ++ni)
                    mma16816(acc[mi][ni], aF[mi], bLf[ni]);
#pragma unroll
            for (int mi = 0; mi < 2; ++mi)
                ldsm4(aF[mi], AL + rowA + mi * 1024 + ko);
#pragma unroll
            for (int mi = 0; mi < 2; ++mi)
#pragma unroll
                for (int ni = 0; ni < 4; ++ni)
                    mma16816(acc[mi][ni], aF[mi], bHf[ni]);
        }
    }

    // ---- epilogue ----
    const int g = L >> 2, t2 = (L & 3) * 2;
    if constexpr (MODE == 1) {
        // shfl-pack fragment pairs into 4-col quads -> red.global.add.v4.f32
        const int half = (L & 3) >> 1;           // cols half*4 .. half*4+3
        const int niA  = (L & 1) * 2;            // this lane issues niA, niA+1
#pragma unroll
        for (int mi = 0; mi < 2; ++mi)
#pragma unroll
            for (int h = 0; h < 2; ++h) {
                int lr = wm + mi * 16 + g + h * 8;
                int d = s_dst[lr];
                float q[4][4];
#pragma unroll
                for (int ni = 0; ni < 4; ++ni) {
                    float vx = acc[mi][ni][h * 2];
                    float vy = acc[mi][ni][h * 2 + 1];
                    float px = __shfl_xor_sync(0xFFFFFFFFu, vx, 1);
                    float py = __shfl_xor_sync(0xFFFFFFFFu, vy, 1);
                    if ((L & 1) == 0) { q[ni][0] = vx; q[ni][1] = vy; q[ni][2] = px; q[ni][3] = py; }
                    else              { q[ni][0] = px; q[ni][1] = py; q[ni][2] = vx; q[ni][3] = vy; }
                }
                if (d >= 0) {
                    float* bp = g_msg + (size_t)d * 128 + coloff + wn + half * 4;
                    asm volatile("red.global.add.v4.f32 [%0], {%1, %2, %3, %4};"
                        :: "l"(bp + niA * 8),
                           "f"(q[niA][0]), "f"(q[niA][1]),
                           "f"(q[niA][2]), "f"(q[niA][3]) : "memory");
                    asm volatile("red.global.add.v4.f32 [%0], {%1, %2, %3, %4};"
                        :: "l"(bp + (niA + 1) * 8),
                           "f"(q[niA + 1][0]), "f"(q[niA + 1][1]),
                           "f"(q[niA + 1][2]), "f"(q[niA + 1][3]) : "memory");
                }
            }
    } else if constexpr (MODE == 2) {
        float2 bb[4];
#pragma unroll
        for (int ni = 0; ni < 4; ++ni)
            bb[ni] = *(const float2*)(bias + coloff + wn + ni * 8 + t2);
#pragma unroll
        for (int mi = 0; mi < 2; ++mi)
#pragma unroll
            for (int h = 0; h < 2; ++h) {
                int r = rowbase + wm + mi * 16 + g + h * 8;
                if (r > N - 1) r = N - 1;
                size_t off = (size_t)r * 256 + coloff + wn + t2;
#pragma unroll
                for (int ni = 0; ni < 4; ++ni) {
                    float vx = tanh_fast(acc[mi][ni][h * 2]     + bb[ni].x);
                    float vy = tanh_fast(acc[mi][ni][h * 2 + 1] + bb[ni].y);
                    __nv_bfloat16 hx = __float2bfloat16(vx);
                    __nv_bfloat16 hy = __float2bfloat16(vy);
                    uint32_t hp = (uint32_t)__bfloat16_as_ushort(hx) |
                                  ((uint32_t)__bfloat16_as_ushort(hy) << 16);
                    uint32_t lp = (uint32_t)__bfloat16_as_ushort(
                                      __float2bfloat16(vx - __bfloat162float(hx))) |
                                  ((uint32_t)__bfloat16_as_ushort(
                                      __float2bfloat16(vy - __bfloat162float(hy))) << 16);
                    *(uint32_t*)((unsigned short*)g_midhi + off + ni * 8) = hp;
                    *(uint32_t*)((unsigned short*)g_midlo + off + ni * 8) = lp;
                }
            }
    } else {
        float2 bb[4];
#pragma unroll
        for (int ni = 0; ni < 4; ++ni)
            bb[ni] = *(const float2*)(bias + coloff + wn + ni * 8 + t2);
#pragma unroll
        for (int mi = 0; mi < 2; ++mi)
#pragma unroll
            for (int h = 0; h < 2; ++h) {
                int r = rowbase + wm + mi * 16 + g + h * 8;
                if (r > N - 1) r = N - 1;
                float* rp = outp + (size_t)r * 128 + coloff + wn + t2;
#pragma unroll
                for (int ni = 0; ni < 4; ++ni) {
                    float2 v;
                    v.x = acc[mi][ni][h * 2]     + bb[ni].x;
                    v.y = acc[mi][ni][h * 2 + 1] + bb[ni].y;
                    *(float2*)(rp + ni * 8) = v;
                }
            }
    }
}

// ---------------------------------------------------------------------------
extern "C" void kernel_launch(void* const* d_in, const int* in_sizes, int n_in,
                              void* d_out, int out_size)
{
    const float* x        = (const float*)d_in[0];
    const int*   src      = (const int*)  d_in[1];
    const int*   dst      = (const int*)  d_in[2];
    const int*   etype    = (const int*)  d_in[3];
    const float* W_rel    = (const float*)d_in[4];
    const float* loop_w   = (const float*)d_in[5];
    const float* rel_bias = (const float*)d_in[6];
    const float* W1       = (const float*)d_in[7];
    const float* b1       = (const float*)d_in[8];
    const float* W2       = (const float*)d_in[9];
    const float* b2       = (const float*)d_in[10];
    float* out = (float*)d_out;

    const int N = in_sizes[0] / 128;
    const int E = in_sizes[1];

    float *msg, *b1eff;
    __nv_bfloat16 *xhi, *xlo, *msghi, *msglo;
    cudaGetSymbolAddress((void**)&msg,   g_msg);
    cudaGetSymbolAddress((void**)&b1eff, g_b1eff);
    cudaGetSymbolAddress((void**)&xhi,   g_xhi);
    cudaGetSymbolAddress((void**)&xlo,   g_xlo);
    cudaGetSymbolAddress((void**)&msghi, g_msghi);
    cudaGetSymbolAddress((void**)&msglo, g_msglo);

    cudaFuncSetAttribute(gemm_rgcn<1>, cudaFuncAttributeMaxDynamicSharedMemorySize, SMEM_DYN);
    cudaFuncSetAttribute(gemm_rgcn<2>, cudaFuncAttributeMaxDynamicSharedMemorySize, SMEM_DYN);
    cudaFuncSetAttribute(gemm_rgcn<3>, cudaFuncAttributeMaxDynamicSharedMemorySize, SMEM_DYN);

    const int P = E + PERM_PAD;
    const int tilesM = (N + 127) / 128;
    const int tilesE = (P + 127) / 128;

    // 1. split x (also zeroes S, g_cnt, g_cur)
    k_split4<<<(N * 32 + 255) / 256, 256>>>(x, xhi, xlo, N * 32);
    // 2. perm init + relation histogram
    k_inithist<<<(P + 255) / 256, 256>>>(etype, E, P);
    // 3. all W_rel transposes+splits (single launch)
    k_prepwrel<<<(R_MAX * 16384 + 255) / 256, 256>>>(W_rel);
    // 4. counting-sort scatter (per-block redundant prefix, segments pad 128)
    k_scatter<<<(E + 255) / 256, 256>>>(etype, E);
    // 5. S += segsum_dst( x[src] @ W_rel[etype] )   (quad REDs)
    gemm_rgcn<1><<<dim3(tilesE, 2), 256, SMEM_DYN>>>(src, dst, etype,
                                                     nullptr, nullptr, N);
    // 6. fold loop_w / rel_bias into W1 -> w1T, b1eff
    k_foldw1<<<(256 * 256 + 256 + 255) / 256, 256>>>(W1, loop_w, rel_bias, b1);
    // 7. W2 transpose + split
    k_prepw2<<<(384 * 128 + 255) / 256, 256>>>(W2);
    // 8. split S
    k_split4m<<<(N * 32 + 255) / 256, 256>>>(msg, msghi, msglo, N * 32);
    // 9. mid = tanh(x @ w1x' + S @ w1m + b1eff) -> bf16 hi/lo
    gemm_rgcn<2><<<dim3(tilesM, 4), 256, SMEM_DYN>>>(nullptr, nullptr, nullptr,
                                                     b1eff, nullptr, N);
    // 10. out = [x, mid] @ W2 + b2
    gemm_rgcn<3><<<dim3(tilesM, 2), 256, SMEM_DYN>>>(nullptr, nullptr, nullptr,
                                                     b2, out, N);
}

// round 12
// speedup vs baseline: 2.4706x; 2.4706x over previous
#include <cuda_runtime.h>
#include <cuda_fp16.h>
#include <stdint.h>

// ---------------------------------------------------------------------------
// RGCN layer on single-pass fp16 mma.sync (plain sm_103 target):
//   S   = segsum_dst( x[src] @ W_rel[etype] )          (REDs into zeroed S)
//   mid = tanh( x @ (W1x + loop_w@W1m) + S @ W1m + (b1 + rel_bias@W1m) )
//   out = [x, mid] @ W2 + b2
// (loop_w / rel_bias folded into W1 — algebraically identical to reference)
//
//   * operands converted once to fp16; fp32 accumulate in mma
//     (fp16 single-pass: per-dot rel err ~2^-12 ~ 1e-4 << 1e-3 threshold,
//      3x fewer tensor MACs than the bf16 hi/lo 3-pass scheme)
//   * weights pre-transposed to [OUT, K]  (mma .row.col B layout)
//   * edges counting-sorted by relation, segments padded to 128
//   * 3-stage single-sync cp.async pipeline (K=32 stages, SW64 swizzle)
//   * CTA tile 128x128, warp tile 64x32, 2 CTAs/SM
//   * edge scatter: shfl-packed red.global.add.v4.f32 (L2-resident S)
// ---------------------------------------------------------------------------

#define N_MAX   100000
#define E_MAX   640000
#define R_MAX   8
#define PERM_PAD (R_MAX * 128)

__device__ float   g_msg  [(size_t)N_MAX * 128];      // S (edge sums, fp32)
__device__ __half  g_xh   [(size_t)N_MAX * 128];
__device__ __half  g_msgh [(size_t)N_MAX * 128];
__device__ __half  g_midh [(size_t)N_MAX * 256];
__device__ __half  g_wrelT[R_MAX * 128 * 128];
__device__ __half  g_w1T  [256 * 256];
__device__ __half  g_w2T  [128 * 384];
__device__ float   g_b1eff[256];
__device__ int g_perm[E_MAX + PERM_PAD];
__device__ int g_cnt[R_MAX];
__device__ int g_cur[R_MAX];

// ---- helpers ---------------------------------------------------------------
__device__ __forceinline__ uint32_t smem_u32(const void* p) {
    uint32_t a;
    asm("{ .reg .u64 t; cvta.to.shared.u64 t, %1; cvt.u32.u64 %0, t; }"
        : "=r"(a) : "l"(p));
    return a;
}

#define CPA16(sm, gp) \
    asm volatile("cp.async.cg.shared.global [%0], [%1], 16;" \
                 :: "r"(sm), "l"(gp) : "memory")
#define CPA_COMMIT() \
    asm volatile("cp.async.commit_group;" ::: "memory")
#define CPA_WAIT1() \
    asm volatile("cp.async.wait_group 1;" ::: "memory")
#define CPA_WAIT0() \
    asm volatile("cp.async.wait_group 0;" ::: "memory")

__device__ __forceinline__ void ldsm4(uint32_t* r, uint32_t addr) {
    asm volatile("ldmatrix.sync.aligned.m8n8.x4.shared.b16 {%0,%1,%2,%3}, [%4];"
        : "=r"(r[0]), "=r"(r[1]), "=r"(r[2]), "=r"(r[3]) : "r"(addr));
}
__device__ __forceinline__ void mma16816(float* d, const uint32_t* a,
                                         const uint32_t* b) {
    asm volatile(
        "mma.sync.aligned.m16n8k16.row.col.f32.f16.f16.f32 "
        "{%0,%1,%2,%3}, {%4,%5,%6,%7}, {%8,%9}, {%0,%1,%2,%3};"
        : "+f"(d[0]), "+f"(d[1]), "+f"(d[2]), "+f"(d[3])
        : "r"(a[0]), "r"(a[1]), "r"(a[2]), "r"(a[3]), "r"(b[0]), "r"(b[1]));
}
__device__ __forceinline__ float tanh_fast(float x) {
    float e;
    asm("ex2.approx.f32 %0, %1;" : "=f"(e) : "f"(x * 2.8853900817779268f));
    return 1.0f - __fdividef(2.0f, e + 1.0f);
}
__device__ __forceinline__ uint32_t pack2h(float a, float b) {
    return (uint32_t)__half_as_ushort(__float2half_rn(a)) |
           ((uint32_t)__half_as_ushort(__float2half_rn(b)) << 16);
}

// ---- fp32 -> fp16 convert; also zeroes S, g_cnt, g_cur ---------------------
__global__ void k_cvtx(const float* __restrict__ in,
                       __half* __restrict__ out16, int n4) {
    int i = blockIdx.x * blockDim.x + threadIdx.x;
    if (blockIdx.x == 0 && threadIdx.x < R_MAX) {
        g_cnt[threadIdx.x] = 0;
        g_cur[threadIdx.x] = 0;
    }
    if (i >= n4) return;
    ((float4*)g_msg)[i] = make_float4(0.f, 0.f, 0.f, 0.f);   // zero S
    float4 v = ((const float4*)in)[i];
    uint2 p;
    p.x = pack2h(v.x, v.y);
    p.y = pack2h(v.z, v.w);
    ((uint2*)out16)[i] = p;
}

// ---- plain fp32 -> fp16 convert (for S) ------------------------------------
__global__ void k_cvt(const float* __restrict__ in,
                      __half* __restrict__ out16, int n4) {
    int i = blockIdx.x * blockDim.x + threadIdx.x;
    if (i >= n4) return;
    float4 v = ((const float4*)in)[i];
    uint2 p;
    p.x = pack2h(v.x, v.y);
    p.y = pack2h(v.z, v.w);
    ((uint2*)out16)[i] = p;
}

// ---- all-relation weight transpose: [R,128,128] -> [R][O,K] fp16 -----------
__global__ void k_prepwrel(const float* __restrict__ in) {
    int i = blockIdx.x * blockDim.x + threadIdx.x;
    if (i >= R_MAX * 128 * 128) return;
    int r = i >> 14, rem = i & 16383;
    int k = rem >> 7, o = rem & 127;
    g_wrelT[(size_t)r * 16384 + (size_t)o * 128 + k] = __float2half_rn(in[i]);
}

// ---- W2 transpose: [384, 128] -> [128, 384] fp16 ---------------------------
__global__ void k_prepw2(const float* __restrict__ in) {
    int i = blockIdx.x * blockDim.x + threadIdx.x;
    if (i >= 384 * 128) return;
    int k = i >> 7, o = i & 127;
    g_w2T[(size_t)o * 384 + k] = __float2half_rn(in[i]);
}

// ---- fold loop_w / rel_bias into W1 (fp32 exact), then fp16 ----------------
__global__ void k_foldw1(const float* __restrict__ W1,
                         const float* __restrict__ loop_w,
                         const float* __restrict__ rel_bias,
                         const float* __restrict__ b1) {
    int i = blockIdx.x * blockDim.x + threadIdx.x;
    if (i < 256 * 256) {
        int k = i >> 8, o = i & 255;
        float s = W1[(size_t)k * 256 + o];
        if (k < 128) {
            const float* lw = loop_w + (size_t)k * 128;
#pragma unroll 4
            for (int j = 0; j < 128; j++)
                s += lw[j] * W1[(size_t)(128 + j) * 256 + o];
        }
        g_w1T[(size_t)o * 256 + k] = __float2half_rn(s);
    } else if (i < 256 * 256 + 256) {
        int o = i - 256 * 256;
        float s = b1[o];
        for (int j = 0; j < 128; j++)
            s += rel_bias[j] * W1[(size_t)(128 + j) * 256 + o];
        g_b1eff[o] = s;
    }
}

// ---- sort: init perm + histogram (g_cnt pre-zeroed by k_cvtx) --------------
__global__ void k_inithist(const int* __restrict__ etype, int E, int P) {
    __shared__ int h[R_MAX];
    int tid = threadIdx.x;
    if (tid < R_MAX) h[tid] = 0;
    __syncthreads();
    int i = blockIdx.x * blockDim.x + tid;
    if (i < P) g_perm[i] = -1;
    if (i < E) atomicAdd(&h[etype[i]], 1);
    __syncthreads();
    if (tid < R_MAX && h[tid]) atomicAdd(&g_cnt[tid], h[tid]);
}
// scatter with per-block redundant padded-prefix (no separate scan launch)
__global__ void k_scatter(const int* __restrict__ etype, int E) {
    __shared__ int h[R_MAX], base[R_MAX], off[R_MAX];
    int tid = threadIdx.x;
    if (tid < R_MAX) {
        h[tid] = 0;
        int o = 0;
        for (int r = 0; r < tid; r++) o += (g_cnt[r] + 127) & ~127;
        off[tid] = o;
    }
    __syncthreads();
    int e = blockIdx.x * blockDim.x + tid;
    int r = -1, rank = 0;
    if (e < E) { r = etype[e]; rank = atomicAdd(&h[r], 1); }
    __syncthreads();
    if (tid < R_MAX && h[tid]) base[tid] = atomicAdd(&g_cur[tid], h[tid]);
    __syncthreads();
    if (e < E) g_perm[off[r] + base[r] + rank] = e;
}

// ---------------------------------------------------------------------------
// Unified fp16 HMMA GEMM. MODE: 1=edge(scatter into S), 2=MLP1, 3=MLP2
// 256 threads = 8 warps (2 m x 4 n); CTA tile 128x128; warp tile 64x32.
// K in 32-wide stages; per stage: A 128rx64B + B 128rx64B = 16KB, SW64
// swizzle; THREE stage buffers, single __syncthreads per stage; 2 CTAs/SM.
// ---------------------------------------------------------------------------
static constexpr int TILE_B  = 8192;                 // 128 rows x 64 B
static constexpr int STAGE_B = 2 * TILE_B;           // 16 KB
static constexpr int NSTAGE  = 3;
static constexpr int SMEM_DYN = 1024 + 2048 + NSTAGE * STAGE_B;

template<int MODE>
__global__ void __launch_bounds__(256, 2)
gemm_rgcn(const int* __restrict__ src, const int* __restrict__ dst,
          const int* __restrict__ etype,
          const float* __restrict__ bias,
          float* __restrict__ outp, int N)
{
    constexpr int CH   = (MODE == 2) ? 8 : (MODE == 3) ? 12 : 4;   // 32-k stages
    constexpr int KTOT = (MODE == 2) ? 256 : (MODE == 3) ? 384 : 128;

    extern __shared__ char dynsmem[];
    uint32_t sb0 = smem_u32(dynsmem);
    uint32_t sb  = (sb0 + 1023) & ~1023u;
    char* smp = dynsmem + (sb - sb0);

    const int tid = threadIdx.x;
    const int coloff = blockIdx.y * 128;
    const int rowbase = blockIdx.x * 128;
    int* s_meta = (int*)smp;
    int* s_src  = (int*)(smp + 16);
    int* s_dst  = (int*)(smp + 528);
    const uint32_t STG0 = sb + 2048;

    int rel = 0;
    if constexpr (MODE == 1) {
        if (tid < 128) {
            int e = g_perm[rowbase + tid];
            s_src[tid] = (e >= 0) ? src[e] : 0;
            s_dst[tid] = (e >= 0) ? dst[e] : -1;
            if (tid == 0) s_meta[0] = (e >= 0) ? etype[e] : -1;
        }
        __syncthreads();
        rel = s_meta[0];
        if (rel < 0) return;                 // fully-padded tile
    }

    // ---- loader geometry: thread covers rows r0 and r0+64, 16B chunk qid
    const int r0 = tid >> 2, qid = tid & 3;
    int arow0, arow1;
    if constexpr (MODE == 1) { arow0 = s_src[r0]; arow1 = s_src[r0 + 64]; }
    else {
        arow0 = rowbase + r0;      if (arow0 > N - 1) arow0 = N - 1;
        arow1 = rowbase + r0 + 64; if (arow1 > N - 1) arow1 = N - 1;
    }
    // SW64 swizzled smem offsets (chunk ^ ((row&6)<<3)); row+64 keeps (row&6)
    const uint32_t sd0 = (uint32_t)r0 * 64 + (uint32_t)((qid * 16) ^ ((r0 & 6) << 3));
    const uint32_t sd1 = sd0 + 64 * 64;

    // ---- fragment geometry
    const int L  = tid & 31, wid = tid >> 5;
    const int wm = (wid & 1) * 64, wn = (wid >> 1) * 32;
    const int lr15 = L & 15;
    const uint32_t swz = (uint32_t)((lr15 & 6) << 3);
    const uint32_t rowA = (uint32_t)(wm + lr15) * 64;
    const uint32_t rowB = (uint32_t)(wn + lr15) * 64;
    uint32_t cbx[2];
#pragma unroll
    for (int ks = 0; ks < 2; ks++)
        cbx[ks] = (uint32_t)(((L >> 4) * 16 + ks * 32)) ^ swz;

    float acc[4][4][4];
#pragma unroll
    for (int mi = 0; mi < 4; mi++)
#pragma unroll
        for (int ni = 0; ni < 4; ni++)
#pragma unroll
            for (int q = 0; q < 4; q++) acc[mi][ni][q] = 0.0f;

    // ---- stage issue: 4 x 16B cp.async into buffer (c % 3)
    auto issue = [&](int c) {
        const __half *pa, *pb;
        size_t ka, abase;
        if (MODE == 2 && c >= 4)      { pa = g_msgh; ka = 128; abase = (size_t)(c - 4) * 32; }
        else if (MODE == 3 && c >= 4) { pa = g_midh; ka = 256; abase = (size_t)(c - 4) * 32; }
        else                          { pa = g_xh;   ka = 128; abase = (size_t)c * 32; }
        if (MODE == 1)      pb = g_wrelT + (size_t)rel * 16384;
        else if (MODE == 2) pb = g_w1T;
        else                pb = g_w2T;
        const size_t a0 = (size_t)arow0 * ka + abase + (size_t)qid * 8;
        const size_t a1 = (size_t)arow1 * ka + abase + (size_t)qid * 8;
        const size_t b0 = (size_t)(coloff + r0) * KTOT + (size_t)c * 32 + (size_t)qid * 8;
        const size_t b1 = b0 + (size_t)64 * KTOT;
        const uint32_t ST = STG0 + (uint32_t)(c % NSTAGE) * STAGE_B;
        const uint32_t A = ST, B = ST + TILE_B;
        CPA16(A + sd0, (const char*)(pa + a0));
        CPA16(A + sd1, (const char*)(pa + a1));
        CPA16(B + sd0, (const char*)(pb + b0));
        CPA16(B + sd1, (const char*)(pb + b1));
        CPA_COMMIT();
    };

    issue(0);
    issue(1);

#pragma unroll 1
    for (int c = 0; c < CH; ++c) {
        if (c + 1 < CH) CPA_WAIT1(); else CPA_WAIT0();
        __syncthreads();           // stage c ready; all warps done with c-1
        if (c + 2 < CH) issue(c + 2);   // writes (c+2)%3 == (c-1)%3: safe

        const uint32_t ST = STG0 + (uint32_t)(c % NSTAGE) * STAGE_B;
        const uint32_t A = ST, B = ST + TILE_B;

#pragma unroll
        for (int ks = 0; ks < 2; ++ks) {
            const uint32_t ko = cbx[ks];
            uint32_t aF[4][4], bF[4][2];
            {
                uint32_t bq[4], bq2[4];
                ldsm4(bq,  B + rowB + ko);
                ldsm4(bq2, B + rowB + 1024 + ko);
                bF[0][0] = bq[0];  bF[0][1] = bq[2];
                bF[1][0] = bq[1];  bF[1][1] = bq[3];
                bF[2][0] = bq2[0]; bF[2][1] = bq2[2];
                bF[3][0] = bq2[1]; bF[3][1] = bq2[3];
            }
#pragma unroll
            for (int mi = 0; mi < 4; ++mi)
                ldsm4(aF[mi], A + rowA + mi * 1024 + ko);
#pragma unroll
            for (int mi = 0; mi < 4; ++mi)
#pragma unroll
                for (int ni = 0; ni < 4; ++ni)
                    mma16816(acc[mi][ni], aF[mi], bF[ni]);
        }
    }

    // ---- epilogue ----
    const int g = L >> 2, t2 = (L & 3) * 2;
    if constexpr (MODE == 1) {
        // shfl-pack fragment pairs into 4-col quads -> red.global.add.v4.f32
        const int half = (L & 3) >> 1;           // cols half*4 .. half*4+3
        const int niA  = (L & 1) * 2;            // this lane issues niA, niA+1
#pragma unroll
        for (int mi = 0; mi < 4; ++mi)
#pragma unroll
            for (int h = 0; h < 2; ++h) {
                int lr = wm + mi * 16 + g + h * 8;
                int d = s_dst[lr];
                float q[4][4];
#pragma unroll
                for (int ni = 0; ni < 4; ++ni) {
                    float vx = acc[mi][ni][h * 2];
                    float vy = acc[mi][ni][h * 2 + 1];
                    float px = __shfl_xor_sync(0xFFFFFFFFu, vx, 1);
                    float py = __shfl_xor_sync(0xFFFFFFFFu, vy, 1);
                    if ((L & 1) == 0) { q[ni][0] = vx; q[ni][1] = vy; q[ni][2] = px; q[ni][3] = py; }
                    else              { q[ni][0] = px; q[ni][1] = py; q[ni][2] = vx; q[ni][3] = vy; }
                }
                if (d >= 0) {
                    float* bp = g_msg + (size_t)d * 128 + wn + half * 4;
                    asm volatile("red.global.add.v4.f32 [%0], {%1, %2, %3, %4};"
                        :: "l"(bp + niA * 8),
                           "f"(q[niA][0]), "f"(q[niA][1]),
                           "f"(q[niA][2]), "f"(q[niA][3]) : "memory");
                    asm volatile("red.global.add.v4.f32 [%0], {%1, %2, %3, %4};"
                        :: "l"(bp + (niA + 1) * 8),
                           "f"(q[niA + 1][0]), "f"(q[niA + 1][1]),
                           "f"(q[niA + 1][2]), "f"(q[niA + 1][3]) : "memory");
                }
            }
    } else if constexpr (MODE == 2) {
        float2 bb[4];
#pragma unroll
        for (int ni = 0; ni < 4; ++ni)
            bb[ni] = *(const float2*)(bias + coloff + wn + ni * 8 + t2);
#pragma unroll
        for (int mi = 0; mi < 4; ++mi)
#pragma unroll
            for (int h = 0; h < 2; ++h) {
                int r = rowbase + wm + mi * 16 + g + h * 8;
                if (r > N - 1) r = N - 1;
                size_t off = (size_t)r * 256 + coloff + wn + t2;
#pragma unroll
                for (int ni = 0; ni < 4; ++ni) {
                    float vx = tanh_fast(acc[mi][ni][h * 2]     + bb[ni].x);
                    float vy = tanh_fast(acc[mi][ni][h * 2 + 1] + bb[ni].y);
                    *(uint32_t*)((unsigned short*)g_midh + off + ni * 8) =
                        pack2h(vx, vy);
                }
            }
    } else {
        float2 bb[4];
#pragma unroll
        for (int ni = 0; ni < 4; ++ni)
            bb[ni] = *(const float2*)(bias + wn + ni * 8 + t2);
#pragma unroll
        for (int mi = 0; mi < 4; ++mi)
#pragma unroll
            for (int h = 0; h < 2; ++h) {
                int r = rowbase + wm + mi * 16 + g + h * 8;
                if (r > N - 1) r = N - 1;
                float* rp = outp + (size_t)r * 128 + wn + t2;
#pragma unroll
                for (int ni = 0; ni < 4; ++ni) {
                    float2 v;
                    v.x = acc[mi][ni][h * 2]     + bb[ni].x;
                    v.y = acc[mi][ni][h * 2 + 1] + bb[ni].y;
                    *(float2*)(rp + ni * 8) = v;
                }
            }
    }
}

// ---------------------------------------------------------------------------
extern "C" void kernel_launch(void* const* d_in, const int* in_sizes, int n_in,
                              void* d_out, int out_size)
{
    const float* x        = (const float*)d_in[0];
    const int*   src      = (const int*)  d_in[1];
    const int*   dst      = (const int*)  d_in[2];
    const int*   etype    = (const int*)  d_in[3];
    const float* W_rel    = (const float*)d_in[4];
    const float* loop_w   = (const float*)d_in[5];
    const float* rel_bias = (const float*)d_in[6];
    const float* W1       = (const float*)d_in[7];
    const float* b1       = (const float*)d_in[8];
    const float* W2       = (const float*)d_in[9];
    const float* b2       = (const float*)d_in[10];
    float* out = (float*)d_out;

    const int N = in_sizes[0] / 128;
    const int E = in_sizes[1];

    float *msg, *b1eff;
    __half *xh, *msgh;
    cudaGetSymbolAddress((void**)&msg,   g_msg);
    cudaGetSymbolAddress((void**)&b1eff, g_b1eff);
    cudaGetSymbolAddress((void**)&xh,    g_xh);
    cudaGetSymbolAddress((void**)&msgh,  g_msgh);

    cudaFuncSetAttribute(gemm_rgcn<1>, cudaFuncAttributeMaxDynamicSharedMemorySize, SMEM_DYN);
    cudaFuncSetAttribute(gemm_rgcn<2>, cudaFuncAttributeMaxDynamicSharedMemorySize, SMEM_DYN);
    cudaFuncSetAttribute(gemm_rgcn<3>, cudaFuncAttributeMaxDynamicSharedMemorySize, SMEM_DYN);

    const int P = E + PERM_PAD;
    const int tilesM = (N + 127) / 128;
    const int tilesE = (P + 127) / 128;

    // 1. convert x to fp16 (also zeroes S, g_cnt, g_cur)
    k_cvtx<<<(N * 32 + 255) / 256, 256>>>(x, xh, N * 32);
    // 2. perm init + relation histogram
    k_inithist<<<(P + 255) / 256, 256>>>(etype, E, P);
    // 3. all W_rel transposes (single launch)
    k_prepwrel<<<(R_MAX * 16384 + 255) / 256, 256>>>(W_rel);
    // 4. counting-sort scatter (per-block redundant prefix, segments pad 128)
    k_scatter<<<(E + 255) / 256, 256>>>(etype, E);
    // 5. S += segsum_dst( x[src] @ W_rel[etype] )   (quad REDs)
    gemm_rgcn<1><<<tilesE, 256, SMEM_DYN>>>(src, dst, etype, nullptr, nullptr, N);
    // 6. fold loop_w / rel_bias into W1 -> w1T, b1eff
    k_foldw1<<<(256 * 256 + 256 + 255) / 256, 256>>>(W1, loop_w, rel_bias, b1);
    // 7. W2 transpose
    k_prepw2<<<(384 * 128 + 255) / 256, 256>>>(W2);
    // 8. convert S to fp16
    k_cvt<<<(N * 32 + 255) / 256, 256>>>(msg, msgh, N * 32);
    // 9. mid = tanh(x @ w1x' + S @ w1m + b1eff) -> fp16
    gemm_rgcn<2><<<dim3(tilesM, 2), 256, SMEM_DYN>>>(nullptr, nullptr, nullptr,
                                                     b1eff, nullptr, N);
    // 10. out = [x, mid] @ W2 + b2
    gemm_rgcn<3><<<tilesM, 256, SMEM_DYN>>>(nullptr, nullptr, nullptr,
                                            b2, out, N);
}

// round 13
// speedup vs baseline: 2.5171x; 1.0189x over previous
#include <cuda_runtime.h>
#include <cuda_fp16.h>
#include <stdint.h>

// ---------------------------------------------------------------------------
// RGCN layer on single-pass fp16 mma.sync (plain sm_103 target):
//   S   = segsum_dst( x[src] @ W_rel[etype] )          (REDs into zeroed S)
//   mid = tanh( x @ (W1x + loop_w@W1m) + S @ W1m + (b1 + rel_bias@W1m) )
//   out = [x, mid] @ W2 + b2
// (loop_w / rel_bias folded into W1 — algebraically identical to reference)
//
//   * operands converted once to fp16; fp32 accumulate in mma
//   * weights pre-transposed to [OUT, K]  (mma .row.col B layout)
//   * edges counting-sorted by relation, segments padded to 128
//   * 4-stage cp.async pipeline, prefetch distance 2 (K=32 stages, SW64)
//   * CTA tile 128x128, warp tile 64x32, 2 CTAs/SM
//   * edge scatter: shfl-packed red.global.add.v4.f32 (L2-resident S)
// ---------------------------------------------------------------------------

#define N_MAX   100000
#define E_MAX   640000
#define R_MAX   8
#define PERM_PAD (R_MAX * 128)

__device__ float   g_msg  [(size_t)N_MAX * 128];      // S (edge sums, fp32)
__device__ __half  g_xh   [(size_t)N_MAX * 128];
__device__ __half  g_msgh [(size_t)N_MAX * 128];
__device__ __half  g_midh [(size_t)N_MAX * 256];
__device__ __half  g_wrelT[R_MAX * 128 * 128];
__device__ __half  g_w1T  [256 * 256];
__device__ __half  g_w2T  [128 * 384];
__device__ float   g_b1eff[256];
__device__ int g_perm[E_MAX + PERM_PAD];
__device__ int g_cnt[R_MAX];
__device__ int g_cur[R_MAX];

// ---- helpers ---------------------------------------------------------------
__device__ __forceinline__ uint32_t smem_u32(const void* p) {
    uint32_t a;
    asm("{ .reg .u64 t; cvta.to.shared.u64 t, %1; cvt.u32.u64 %0, t; }"
        : "=r"(a) : "l"(p));
    return a;
}

#define CPA16(sm, gp) \
    asm volatile("cp.async.cg.shared.global [%0], [%1], 16;" \
                 :: "r"(sm), "l"(gp) : "memory")
#define CPA_COMMIT() \
    asm volatile("cp.async.commit_group;" ::: "memory")
#define CPA_WAIT2() \
    asm volatile("cp.async.wait_group 2;" ::: "memory")
#define CPA_WAIT1() \
    asm volatile("cp.async.wait_group 1;" ::: "memory")
#define CPA_WAIT0() \
    asm volatile("cp.async.wait_group 0;" ::: "memory")

__device__ __forceinline__ void ldsm4(uint32_t* r, uint32_t addr) {
    asm volatile("ldmatrix.sync.aligned.m8n8.x4.shared.b16 {%0,%1,%2,%3}, [%4];"
        : "=r"(r[0]), "=r"(r[1]), "=r"(r[2]), "=r"(r[3]) : "r"(addr));
}
__device__ __forceinline__ void mma16816(float* d, const uint32_t* a,
                                         const uint32_t* b) {
    asm volatile(
        "mma.sync.aligned.m16n8k16.row.col.f32.f16.f16.f32 "
        "{%0,%1,%2,%3}, {%4,%5,%6,%7}, {%8,%9}, {%0,%1,%2,%3};"
        : "+f"(d[0]), "+f"(d[1]), "+f"(d[2]), "+f"(d[3])
        : "r"(a[0]), "r"(a[1]), "r"(a[2]), "r"(a[3]), "r"(b[0]), "r"(b[1]));
}
__device__ __forceinline__ float tanh_fast(float x) {
    float e;
    asm("ex2.approx.f32 %0, %1;" : "=f"(e) : "f"(x * 2.8853900817779268f));
    return 1.0f - __fdividef(2.0f, e + 1.0f);
}
__device__ __forceinline__ uint32_t pack2h(float a, float b) {
    return (uint32_t)__half_as_ushort(__float2half_rn(a)) |
           ((uint32_t)__half_as_ushort(__float2half_rn(b)) << 16);
}

// ---- fp32 -> fp16 convert; also zeroes S, g_cnt, g_cur ---------------------
__global__ void k_cvtx(const float* __restrict__ in,
                       __half* __restrict__ out16, int n4) {
    int i = blockIdx.x * blockDim.x + threadIdx.x;
    if (blockIdx.x == 0 && threadIdx.x < R_MAX) {
        g_cnt[threadIdx.x] = 0;
        g_cur[threadIdx.x] = 0;
    }
    if (i >= n4) return;
    ((float4*)g_msg)[i] = make_float4(0.f, 0.f, 0.f, 0.f);   // zero S
    float4 v = ((const float4*)in)[i];
    uint2 p;
    p.x = pack2h(v.x, v.y);
    p.y = pack2h(v.z, v.w);
    ((uint2*)out16)[i] = p;
}

// ---- plain fp32 -> fp16 convert (for S) ------------------------------------
__global__ void k_cvt(const float* __restrict__ in,
                      __half* __restrict__ out16, int n4) {
    int i = blockIdx.x * blockDim.x + threadIdx.x;
    if (i >= n4) return;
    float4 v = ((const float4*)in)[i];
    uint2 p;
    p.x = pack2h(v.x, v.y);
    p.y = pack2h(v.z, v.w);
    ((uint2*)out16)[i] = p;
}

// ---- merged prep: perm init + relation histogram + W_rel transpose ---------
__global__ void k_prep(const int* __restrict__ etype, int E, int P,
                       const float* __restrict__ wrel) {
    __shared__ int h[R_MAX];
    int tid = threadIdx.x;
    if (tid < R_MAX) h[tid] = 0;
    __syncthreads();
    int i = blockIdx.x * blockDim.x + tid;
    if (i < P) g_perm[i] = -1;
    if (i < E) atomicAdd(&h[etype[i]], 1);
    if (i < R_MAX * 128 * 128) {
        int r = i >> 14, rem = i & 16383;
        int k = rem >> 7, o = rem & 127;
        g_wrelT[(size_t)r * 16384 + (size_t)o * 128 + k] =
            __float2half_rn(wrel[i]);
    }
    __syncthreads();
    if (tid < R_MAX && h[tid]) atomicAdd(&g_cnt[tid], h[tid]);
}

// ---- W2 transpose: [384, 128] -> [128, 384] fp16 ---------------------------
__global__ void k_prepw2(const float* __restrict__ in) {
    int i = blockIdx.x * blockDim.x + threadIdx.x;
    if (i >= 384 * 128) return;
    int k = i >> 7, o = i & 127;
    g_w2T[(size_t)o * 384 + k] = __float2half_rn(in[i]);
}

// ---- fold loop_w / rel_bias into W1 (fp32 exact), then fp16 ----------------
__global__ void k_foldw1(const float* __restrict__ W1,
                         const float* __restrict__ loop_w,
                         const float* __restrict__ rel_bias,
                         const float* __restrict__ b1) {
    int i = blockIdx.x * blockDim.x + threadIdx.x;
    if (i < 256 * 256) {
        int k = i >> 8, o = i & 255;
        float s = W1[(size_t)k * 256 + o];
        if (k < 128) {
            const float* lw = loop_w + (size_t)k * 128;
#pragma unroll 4
            for (int j = 0; j < 128; j++)
                s += lw[j] * W1[(size_t)(128 + j) * 256 + o];
        }
        g_w1T[(size_t)o * 256 + k] = __float2half_rn(s);
    } else if (i < 256 * 256 + 256) {
        int o = i - 256 * 256;
        float s = b1[o];
        for (int j = 0; j < 128; j++)
            s += rel_bias[j] * W1[(size_t)(128 + j) * 256 + o];
        g_b1eff[o] = s;
    }
}

// ---- counting-sort scatter (per-block redundant padded prefix) ------------
__global__ void k_scatter(const int* __restrict__ etype, int E) {
    __shared__ int h[R_MAX], base[R_MAX], off[R_MAX];
    int tid = threadIdx.x;
    if (tid < R_MAX) {
        h[tid] = 0;
        int o = 0;
        for (int r = 0; r < tid; r++) o += (g_cnt[r] + 127) & ~127;
        off[tid] = o;
    }
    __syncthreads();
    int e = blockIdx.x * blockDim.x + tid;
    int r = -1, rank = 0;
    if (e < E) { r = etype[e]; rank = atomicAdd(&h[r], 1); }
    __syncthreads();
    if (tid < R_MAX && h[tid]) base[tid] = atomicAdd(&g_cur[tid], h[tid]);
    __syncthreads();
    if (e < E) g_perm[off[r] + base[r] + rank] = e;
}

// ---------------------------------------------------------------------------
// Unified fp16 HMMA GEMM. MODE: 1=edge(scatter into S), 2=MLP1, 3=MLP2
// 256 threads = 8 warps (2 m x 4 n); CTA tile 128x128; warp tile 64x32.
// K in 32-wide stages; per stage: A 128rx64B + B 128rx64B = 16KB, SW64
// swizzle; FOUR stage buffers, prefetch distance 2, one sync per stage.
// ---------------------------------------------------------------------------
static constexpr int TILE_B  = 8192;                 // 128 rows x 64 B
static constexpr int STAGE_B = 2 * TILE_B;           // 16 KB
static constexpr int NSTAGE  = 4;
static constexpr int SMEM_DYN = 1024 + 2048 + NSTAGE * STAGE_B;

template<int MODE>
__global__ void __launch_bounds__(256, 2)
gemm_rgcn(const int* __restrict__ src, const int* __restrict__ dst,
          const int* __restrict__ etype,
          const float* __restrict__ bias,
          float* __restrict__ outp, int N)
{
    constexpr int CH   = (MODE == 2) ? 8 : (MODE == 3) ? 12 : 4;   // 32-k stages
    constexpr int KTOT = (MODE == 2) ? 256 : (MODE == 3) ? 384 : 128;

    extern __shared__ char dynsmem[];
    uint32_t sb0 = smem_u32(dynsmem);
    uint32_t sb  = (sb0 + 1023) & ~1023u;
    char* smp = dynsmem + (sb - sb0);

    const int tid = threadIdx.x;
    const int coloff = blockIdx.y * 128;
    const int rowbase = blockIdx.x * 128;
    int* s_meta = (int*)smp;
    int* s_src  = (int*)(smp + 16);
    int* s_dst  = (int*)(smp + 528);
    const uint32_t STG0 = sb + 2048;

    int rel = 0;
    if constexpr (MODE == 1) {
        if (tid < 128) {
            int e = g_perm[rowbase + tid];
            s_src[tid] = (e >= 0) ? src[e] : 0;
            s_dst[tid] = (e >= 0) ? dst[e] : -1;
            if (tid == 0) s_meta[0] = (e >= 0) ? etype[e] : -1;
        }
        __syncthreads();
        rel = s_meta[0];
        if (rel < 0) return;                 // fully-padded tile
    }

    // ---- loader geometry: thread covers rows r0 and r0+64, 16B chunk qid
    const int r0 = tid >> 2, qid = tid & 3;
    int arow0, arow1;
    if constexpr (MODE == 1) { arow0 = s_src[r0]; arow1 = s_src[r0 + 64]; }
    else {
        arow0 = rowbase + r0;      if (arow0 > N - 1) arow0 = N - 1;
        arow1 = rowbase + r0 + 64; if (arow1 > N - 1) arow1 = N - 1;
    }
    // SW64 swizzled smem offsets (chunk ^ ((row&6)<<3)); row+64 keeps (row&6)
    const uint32_t sd0 = (uint32_t)r0 * 64 + (uint32_t)((qid * 16) ^ ((r0 & 6) << 3));
    const uint32_t sd1 = sd0 + 64 * 64;

    // ---- fragment geometry
    const int L  = tid & 31, wid = tid >> 5;
    const int wm = (wid & 1) * 64, wn = (wid >> 1) * 32;
    const int lr15 = L & 15;
    const uint32_t swz = (uint32_t)((lr15 & 6) << 3);
    const uint32_t rowA = (uint32_t)(wm + lr15) * 64;
    const uint32_t rowB = (uint32_t)(wn + lr15) * 64;
    uint32_t cbx[2];
#pragma unroll
    for (int ks = 0; ks < 2; ks++)
        cbx[ks] = (uint32_t)(((L >> 4) * 16 + ks * 32)) ^ swz;

    float acc[4][4][4];
#pragma unroll
    for (int mi = 0; mi < 4; mi++)
#pragma unroll
        for (int ni = 0; ni < 4; ni++)
#pragma unroll
            for (int q = 0; q < 4; q++) acc[mi][ni][q] = 0.0f;

    // ---- stage issue: 4 x 16B cp.async into buffer (c % 4)
    auto issue = [&](int c) {
        const __half *pa, *pb;
        size_t ka, abase;
        if (MODE == 2 && c >= 4)      { pa = g_msgh; ka = 128; abase = (size_t)(c - 4) * 32; }
        else if (MODE == 3 && c >= 4) { pa = g_midh; ka = 256; abase = (size_t)(c - 4) * 32; }
        else                          { pa = g_xh;   ka = 128; abase = (size_t)c * 32; }
        if (MODE == 1)      pb = g_wrelT + (size_t)rel * 16384;
        else if (MODE == 2) pb = g_w1T;
        else                pb = g_w2T;
        const size_t a0 = (size_t)arow0 * ka + abase + (size_t)qid * 8;
        const size_t a1 = (size_t)arow1 * ka + abase + (size_t)qid * 8;
        const size_t b0 = (size_t)(coloff + r0) * KTOT + (size_t)c * 32 + (size_t)qid * 8;
        const size_t b1 = b0 + (size_t)64 * KTOT;
        const uint32_t ST = STG0 + (uint32_t)(c % NSTAGE) * STAGE_B;
        const uint32_t A = ST, B = ST + TILE_B;
        CPA16(A + sd0, (const char*)(pa + a0));
        CPA16(A + sd1, (const char*)(pa + a1));
        CPA16(B + sd0, (const char*)(pb + b0));
        CPA16(B + sd1, (const char*)(pb + b1));
        CPA_COMMIT();
    };

    issue(0);
    issue(1);
    issue(2);

#pragma unroll 1
    for (int c = 0; c < CH; ++c) {
        const int rem = CH - 1 - c;
        if (rem >= 2)      CPA_WAIT2();     // stages <= c complete
        else if (rem == 1) CPA_WAIT1();
        else               CPA_WAIT0();
        __syncthreads();           // stage c ready; all warps done with c-1
        if (c + 3 < CH) issue(c + 3);   // writes (c+3)%4 == (c-1)%4: safe

        const uint32_t ST = STG0 + (uint32_t)(c % NSTAGE) * STAGE_B;
        const uint32_t A = ST, B = ST + TILE_B;

#pragma unroll
        for (int ks = 0; ks < 2; ++ks) {
            const uint32_t ko = cbx[ks];
            uint32_t aF[4][4], bF[4][2];
            {
                uint32_t bq[4], bq2[4];
                ldsm4(bq,  B + rowB + ko);
                ldsm4(bq2, B + rowB + 1024 + ko);
                bF[0][0] = bq[0];  bF[0][1] = bq[2];
                bF[1][0] = bq[1];  bF[1][1] = bq[3];
                bF[2][0] = bq2[0]; bF[2][1] = bq2[2];
                bF[3][0] = bq2[1]; bF[3][1] = bq2[3];
            }
#pragma unroll
            for (int mi = 0; mi < 4; ++mi)
                ldsm4(aF[mi], A + rowA + mi * 1024 + ko);
#pragma unroll
            for (int mi = 0; mi < 4; ++mi)
#pragma unroll
                for (int ni = 0; ni < 4; ++ni)
                    mma16816(acc[mi][ni], aF[mi], bF[ni]);
        }
    }

    // ---- epilogue ----
    const int g = L >> 2, t2 = (L & 3) * 2;
    if constexpr (MODE == 1) {
        // shfl-pack fragment pairs into 4-col quads -> red.global.add.v4.f32
        const int half = (L & 3) >> 1;           // cols half*4 .. half*4+3
        const int niA  = (L & 1) * 2;            // this lane issues niA, niA+1
#pragma unroll
        for (int mi = 0; mi < 4; ++mi)
#pragma unroll
            for (int h = 0; h < 2; ++h) {
                int lr = wm + mi * 16 + g + h * 8;
                int d = s_dst[lr];
                float q[4][4];
#pragma unroll
                for (int ni = 0; ni < 4; ++ni) {
                    float vx = acc[mi][ni][h * 2];
                    float vy = acc[mi][ni][h * 2 + 1];
                    float px = __shfl_xor_sync(0xFFFFFFFFu, vx, 1);
                    float py = __shfl_xor_sync(0xFFFFFFFFu, vy, 1);
                    if ((L & 1) == 0) { q[ni][0] = vx; q[ni][1] = vy; q[ni][2] = px; q[ni][3] = py; }
                    else              { q[ni][0] = px; q[ni][1] = py; q[ni][2] = vx; q[ni][3] = vy; }
                }
                if (d >= 0) {
                    float* bp = g_msg + (size_t)d * 128 + wn + half * 4;
                    asm volatile("red.global.add.v4.f32 [%0], {%1, %2, %3, %4};"
                        :: "l"(bp + niA * 8),
                           "f"(q[niA][0]), "f"(q[niA][1]),
                           "f"(q[niA][2]), "f"(q[niA][3]) : "memory");
                    asm volatile("red.global.add.v4.f32 [%0], {%1, %2, %3, %4};"
                        :: "l"(bp + (niA + 1) * 8),
                           "f"(q[niA + 1][0]), "f"(q[niA + 1][1]),
                           "f"(q[niA + 1][2]), "f"(q[niA + 1][3]) : "memory");
                }
            }
    } else if constexpr (MODE == 2) {
        float2 bb[4];
#pragma unroll
        for (int ni = 0; ni < 4; ++ni)
            bb[ni] = *(const float2*)(bias + coloff + wn + ni * 8 + t2);
#pragma unroll
        for (int mi = 0; mi < 4; ++mi)
#pragma unroll
            for (int h = 0; h < 2; ++h) {
                int r = rowbase + wm + mi * 16 + g + h * 8;
                if (r > N - 1) r = N - 1;
                size_t off = (size_t)r * 256 + coloff + wn + t2;
#pragma unroll
                for (int ni = 0; ni < 4; ++ni) {
                    float vx = tanh_fast(acc[mi][ni][h * 2]     + bb[ni].x);
                    float vy = tanh_fast(acc[mi][ni][h * 2 + 1] + bb[ni].y);
                    *(uint32_t*)((unsigned short*)g_midh + off + ni * 8) =
                        pack2h(vx, vy);
                }
            }
    } else {
        float2 bb[4];
#pragma unroll
        for (int ni = 0; ni < 4; ++ni)
            bb[ni] = *(const float2*)(bias + wn + ni * 8 + t2);
#pragma unroll
        for (int mi = 0; mi < 4; ++mi)
#pragma unroll
            for (int h = 0; h < 2; ++h) {
                int r = rowbase + wm + mi * 16 + g + h * 8;
                if (r > N - 1) r = N - 1;
                float* rp = outp + (size_t)r * 128 + wn + t2;
#pragma unroll
                for (int ni = 0; ni < 4; ++ni) {
                    float2 v;
                    v.x = acc[mi][ni][h * 2]     + bb[ni].x;
                    v.y = acc[mi][ni][h * 2 + 1] + bb[ni].y;
                    *(float2*)(rp + ni * 8) = v;
                }
            }
    }
}

// ---------------------------------------------------------------------------
extern "C" void kernel_launch(void* const* d_in, const int* in_sizes, int n_in,
                              void* d_out, int out_size)
{
    const float* x        = (const float*)d_in[0];
    const int*   src      = (const int*)  d_in[1];
    const int*   dst      = (const int*)  d_in[2];
    const int*   etype    = (const int*)  d_in[3];
    const float* W_rel    = (const float*)d_in[4];
    const float* loop_w   = (const float*)d_in[5];
    const float* rel_bias = (const float*)d_in[6];
    const float* W1       = (const float*)d_in[7];
    const float* b1       = (const float*)d_in[8];
    const float* W2       = (const float*)d_in[9];
    const float* b2       = (const float*)d_in[10];
    float* out = (float*)d_out;

    const int N = in_sizes[0] / 128;
    const int E = in_sizes[1];

    float *msg, *b1eff;
    __half *xh, *msgh;
    cudaGetSymbolAddress((void**)&msg,   g_msg);
    cudaGetSymbolAddress((void**)&b1eff, g_b1eff);
    cudaGetSymbolAddress((void**)&xh,    g_xh);
    cudaGetSymbolAddress((void**)&msgh,  g_msgh);

    cudaFuncSetAttribute(gemm_rgcn<1>, cudaFuncAttributeMaxDynamicSharedMemorySize, SMEM_DYN);
    cudaFuncSetAttribute(gemm_rgcn<2>, cudaFuncAttributeMaxDynamicSharedMemorySize, SMEM_DYN);
    cudaFuncSetAttribute(gemm_rgcn<3>, cudaFuncAttributeMaxDynamicSharedMemorySize, SMEM_DYN);

    const int P = E + PERM_PAD;
    const int tilesM = (N + 127) / 128;
    const int tilesE = (P + 127) / 128;

    // 1. convert x to fp16 (also zeroes S, g_cnt, g_cur)
    k_cvtx<<<(N * 32 + 255) / 256, 256>>>(x, xh, N * 32);
    // 2. perm init + relation histogram + W_rel transpose (merged)
    k_prep<<<(P + 255) / 256, 256>>>(etype, E, P, W_rel);
    // 3. counting-sort scatter
    k_scatter<<<(E + 255) / 256, 256>>>(etype, E);
    // 4. S += segsum_dst( x[src] @ W_rel[etype] )  -- PROFILED LAUNCH SLOT
    gemm_rgcn<1><<<tilesE, 256, SMEM_DYN>>>(src, dst, etype, nullptr, nullptr, N);
    // 5. fold loop_w / rel_bias into W1 -> w1T, b1eff
    k_foldw1<<<(256 * 256 + 256 + 255) / 256, 256>>>(W1, loop_w, rel_bias, b1);
    // 6. W2 transpose
    k_prepw2<<<(384 * 128 + 255) / 256, 256>>>(W2);
    // 7. convert S to fp16
    k_cvt<<<(N * 32 + 255) / 256, 256>>>(msg, msgh, N * 32);
    // 8. mid = tanh(x @ w1x' + S @ w1m + b1eff) -> fp16
    gemm_rgcn<2><<<dim3(tilesM, 2), 256, SMEM_DYN>>>(nullptr, nullptr, nullptr,
                                                     b1eff, nullptr, N);
    // 9. out = [x, mid] @ W2 + b2
    gemm_rgcn<3><<<tilesM, 256, SMEM_DYN>>>(nullptr, nullptr, nullptr,
                                            b2, out, N);
}